// round 6
// baseline (speedup 1.0000x reference)
#include <cuda_runtime.h>

// Top-K (K=5000) of 50M floats, values output in original-index order.
//
// Fast path (3 launches total):
//   1. spec_compact: stream x >= 3.6 (~8K candidates for N(0,1)), also builds
//      the 4096-bin MSB-key histogram of candidates (RED hidden under DRAM).
//   2. fallback (idle ~1us normally): one block rebuilds full histogram and
//      recompacts if speculation failed — correctness for arbitrary inputs.
//   3. select: one block, exact radix selection (levels 2+3; level 1 from the
//      prebuilt histogram) + index tie-break, then bitonic sort of the K
//      selected pairs by original index in smem, writes out directly, and
//      resets all state for the next graph replay.

#define CAP      (1 << 21)      // global candidate capacity
#define SMCAP    12288          // candidates held in smem by select_kernel
#define TIECAP   4096
#define BINS     4096
#define NP       8192           // bitonic sort size (power of 2 >= K)
#define SPEC_VAL 3.6f
#define FULLMASK 0xFFFFFFFFu
#define NEG_INF  (-3.402823466e38f)

__device__ unsigned g_hist[BINS];
__device__ unsigned g_cand_count;
__device__ float    g_cand_val[CAP];
__device__ int      g_cand_idx[CAP];

__device__ __forceinline__ unsigned fkey(float f) {
    unsigned u = __float_as_uint(f);
    return (u & 0x80000000u) ? ~u : (u | 0x80000000u);
}

// ------------------------------------------ warp-aggregated emit + hist RED
__device__ __forceinline__ void emit4(bool p0, bool p1, bool p2, bool p3,
                                      float4 v, int bi, int lane) {
    int cnt = (int)p0 + (int)p1 + (int)p2 + (int)p3;
    if (!__ballot_sync(FULLMASK, cnt > 0)) return;
    int pre = cnt;
    #pragma unroll
    for (int o = 1; o < 32; o <<= 1) {
        int u = __shfl_up_sync(FULLMASK, pre, o);
        if (lane >= o) pre += u;
    }
    int tot = __shfl_sync(FULLMASK, pre, 31);
    int base = 0;
    if (lane == 31) base = (int)atomicAdd(&g_cand_count, (unsigned)tot);
    base = __shfl_sync(FULLMASK, base, 31);
    int off = base + pre - cnt;
    if (p0) { if (off < CAP) { g_cand_val[off] = v.x; g_cand_idx[off] = bi;
                               atomicAdd(&g_hist[fkey(v.x) >> 20], 1u); } off++; }
    if (p1) { if (off < CAP) { g_cand_val[off] = v.y; g_cand_idx[off] = bi + 1;
                               atomicAdd(&g_hist[fkey(v.y) >> 20], 1u); } off++; }
    if (p2) { if (off < CAP) { g_cand_val[off] = v.z; g_cand_idx[off] = bi + 2;
                               atomicAdd(&g_hist[fkey(v.z) >> 20], 1u); } off++; }
    if (p3) { if (off < CAP) { g_cand_val[off] = v.w; g_cand_idx[off] = bi + 3;
                               atomicAdd(&g_hist[fkey(v.w) >> 20], 1u); } off++; }
}

// ------------------------------------------------- pass 1: speculative compact
__global__ void spec_compact_kernel(const float4* __restrict__ x4, int n4,
                                    const float* __restrict__ x, int n) {
    int t = blockIdx.x * blockDim.x + threadIdx.x;
    int stride = gridDim.x * blockDim.x;
    int lane = threadIdx.x & 31;
    int iters = (n4 + stride - 1) / stride;    // uniform across all threads

    const float4 sent = make_float4(NEG_INF, NEG_INF, NEG_INF, NEG_INF);
    for (int k = 0; k < iters; k += 4) {
        int i0 = t + (k    ) * stride;
        int i1 = t + (k + 1) * stride;
        int i2 = t + (k + 2) * stride;
        int i3 = t + (k + 3) * stride;
        float4 a = (i0 < n4) ? x4[i0] : sent;
        float4 b = (i1 < n4) ? x4[i1] : sent;
        float4 c = (i2 < n4) ? x4[i2] : sent;
        float4 d = (i3 < n4) ? x4[i3] : sent;
        float m = fmaxf(fmaxf(fmaxf(a.x, a.y), fmaxf(a.z, a.w)),
                        fmaxf(fmaxf(b.x, b.y), fmaxf(b.z, b.w)));
        m = fmaxf(m, fmaxf(fmaxf(fmaxf(c.x, c.y), fmaxf(c.z, c.w)),
                           fmaxf(fmaxf(d.x, d.y), fmaxf(d.z, d.w))));
        if (__ballot_sync(FULLMASK, m >= SPEC_VAL)) {
            emit4(a.x >= SPEC_VAL, a.y >= SPEC_VAL, a.z >= SPEC_VAL, a.w >= SPEC_VAL, a, i0 * 4, lane);
            emit4(b.x >= SPEC_VAL, b.y >= SPEC_VAL, b.z >= SPEC_VAL, b.w >= SPEC_VAL, b, i1 * 4, lane);
            emit4(c.x >= SPEC_VAL, c.y >= SPEC_VAL, c.z >= SPEC_VAL, c.w >= SPEC_VAL, c, i2 * 4, lane);
            emit4(d.x >= SPEC_VAL, d.y >= SPEC_VAL, d.z >= SPEC_VAL, d.w >= SPEC_VAL, d, i3 * 4, lane);
        }
    }
    // scalar tail (n % 4 elements)
    if (blockIdx.x == 0 && (int)threadIdx.x < (n - n4 * 4)) {
        int idx = n4 * 4 + threadIdx.x;
        float f = x[idx];
        if (f >= SPEC_VAL) {
            unsigned off = atomicAdd(&g_cand_count, 1u);
            if (off < CAP) {
                g_cand_val[off] = f; g_cand_idx[off] = idx;
                atomicAdd(&g_hist[fkey(f) >> 20], 1u);
            }
        }
    }
}

// suffix-select over smem hist (1024 threads): find bin B with
// cnt_ge(B) >= R > cnt_ge(B+1); write B and residual rank R-cnt_gt(B).
template <int NB>
__device__ void suffix_select(unsigned* h, unsigned* scan, unsigned R,
                              unsigned* outB, unsigned* outR) {
    const int BPT = (NB >= 1024) ? NB / 1024 : 1;
    int t = threadIdx.x;
    unsigned local = 0;
    if (NB >= 1024) {
        #pragma unroll
        for (int j = 0; j < BPT; j++) local += h[t * BPT + j];
    } else {
        local = (t < NB) ? h[t] : 0u;
    }
    scan[t] = local;
    __syncthreads();
    for (int off = 1; off < 1024; off <<= 1) {
        unsigned v = scan[t] + ((t + off < 1024) ? scan[t + off] : 0u);
        __syncthreads();
        scan[t] = v;
        __syncthreads();
    }
    unsigned cum = scan[t] - local;   // strictly above this thread's range
    if (NB >= 1024 || t < NB) {
        #pragma unroll
        for (int j = BPT - 1; j >= 0; j--) {
            int b = t * BPT + j;
            unsigned c = h[b];
            unsigned cg = cum + c;
            if (cg >= R && cum < R) { *outB = (unsigned)b; *outR = R - cum; }
            cum = cg;
        }
    }
    __syncthreads();
}

// ------------------------------------------------- fallback (single block)
__global__ void fallback_kernel(const float4* __restrict__ x4, int n4,
                                const float* __restrict__ x, int n, int K) {
    unsigned cc = g_cand_count;
    if (cc >= (unsigned)K && cc <= (unsigned)CAP) return;   // uniform branch

    __shared__ unsigned h[BINS];
    __shared__ unsigned scan[1024];
    __shared__ unsigned outB, outR;
    int t = threadIdx.x;
    for (int i = t; i < BINS; i += 1024) h[i] = 0;
    __syncthreads();
    for (int i = t; i < n4; i += 1024) {
        float4 v = x4[i];
        atomicAdd(&h[fkey(v.x) >> 20], 1u);
        atomicAdd(&h[fkey(v.y) >> 20], 1u);
        atomicAdd(&h[fkey(v.z) >> 20], 1u);
        atomicAdd(&h[fkey(v.w) >> 20], 1u);
    }
    for (int i = n4 * 4 + t; i < n; i += 1024)
        atomicAdd(&h[fkey(x[i]) >> 20], 1u);
    __syncthreads();
    // overwrite polluted g_hist with the full-data histogram (level-1 source)
    for (int i = t; i < BINS; i += 1024) g_hist[i] = h[i];
    suffix_select<BINS>(h, scan, (unsigned)K, &outB, &outR);
    if (t == 0) g_cand_count = 0;
    __syncthreads();
    unsigned b = outB;
    for (int i = t; i < n; i += 1024) {
        float f = x[i];
        if ((fkey(f) >> 20) >= b) {
            unsigned off = atomicAdd(&g_cand_count, 1u);
            if (off < CAP) { g_cand_val[off] = f; g_cand_idx[off] = i; }
        }
    }
}

// ------------------------------------------------- select + sort + write
// Dynamic smem layout:
//   [SMCAP floats sval][SMCAP ints sidx][BINS u32 h][1024 u32 scan]
//   [NP ints srtIdx][NP floats srtVal]
__global__ void select_kernel(float* __restrict__ out, int K) {
    extern __shared__ unsigned char dyn[];
    float*    sval   = (float*)dyn;
    int*      sidx   = (int*)(dyn + SMCAP * 4);
    unsigned* h      = (unsigned*)(dyn + SMCAP * 8);
    unsigned* scan   = (unsigned*)(dyn + SMCAP * 8 + BINS * 4);
    int*      srtIdx = (int*)(dyn + SMCAP * 8 + BINS * 4 + 1024 * 4);
    float*    srtVal = (float*)(dyn + SMCAP * 8 + BINS * 4 + 1024 * 4 + NP * 4);

    __shared__ unsigned sB, sR;
    __shared__ unsigned sB1, sR1, sB2, sR2, sK3;
    __shared__ unsigned sTK;
    __shared__ unsigned sTieCount;
    __shared__ int      sTieIdx[TIECAP];
    __shared__ int      sTieThresh;
    __shared__ unsigned sSelCount;

    int t = threadIdx.x;
    unsigned cc = g_cand_count;
    int M = (int)(cc < (unsigned)CAP ? cc : (unsigned)CAP);
    bool inSmem = (M <= SMCAP);

    const float* pv;
    const int*   pi;
    if (inSmem) {
        for (int i = t; i < M; i += 1024) { sval[i] = g_cand_val[i]; sidx[i] = g_cand_idx[i]; }
        pv = sval; pi = sidx;
    } else {
        pv = g_cand_val; pi = g_cand_idx;
    }
    for (int i = t; i < BINS; i += 1024) h[i] = g_hist[i];
    if (t == 0) sSelCount = 0;
    __syncthreads();

    // ---- level 1: prebuilt histogram of top 12 key bits
    suffix_select<BINS>(h, scan, (unsigned)K, &sB, &sR);
    if (t == 0) { sB1 = sB; sR1 = sR; }
    __syncthreads();
    unsigned B1 = sB1, R1 = sR1;

    // ---- level 2: bits 19..8
    for (int i = t; i < BINS; i += 1024) h[i] = 0;
    __syncthreads();
    for (int i = t; i < M; i += 1024) {
        unsigned k = fkey(pv[i]);
        if ((k >> 20) == B1) atomicAdd(&h[(k >> 8) & 0xFFFu], 1u);
    }
    __syncthreads();
    suffix_select<BINS>(h, scan, R1, &sB, &sR);
    if (t == 0) { sB2 = sB; sR2 = sR; }
    __syncthreads();
    unsigned B2 = sB2, R2 = sR2;
    unsigned top24 = (B1 << 12) | B2;

    // ---- level 3: bits 7..0
    for (int i = t; i < 256; i += 1024) h[i] = 0;
    __syncthreads();
    for (int i = t; i < M; i += 1024) {
        unsigned k = fkey(pv[i]);
        if ((k >> 8) == top24) atomicAdd(&h[k & 0xFFu], 1u);
    }
    __syncthreads();
    suffix_select<256>(h, scan, R2, &sB, &sR);
    if (t == 0) {
        sK3 = sR;
        sTK = (B1 << 20) | (B2 << 8) | sB;
        sTieCount = 0;
        sTieThresh = -1;
    }
    __syncthreads();
    unsigned TK = sTK, K3 = sK3;

    // ---- collect indices tied at the exact K-th key
    for (int i = t; i < M; i += 1024) {
        if (fkey(pv[i]) == TK) {
            unsigned p = atomicAdd(&sTieCount, 1u);
            if (p < (unsigned)TIECAP) sTieIdx[p] = pi[i];
        }
    }
    __syncthreads();
    int T = (int)(sTieCount < (unsigned)TIECAP ? sTieCount : (unsigned)TIECAP);
    // tie-break: keep the K3 smallest indices among ties; find the cutoff index
    for (int i = t; i < T; i += 1024) {
        int mi = sTieIdx[i];
        int r = 0;
        for (int j = 0; j < T; j++) r += (int)(sTieIdx[j] < mi);
        if (r == (int)K3 - 1) sTieThresh = mi;
    }
    __syncthreads();
    int tieThresh = sTieThresh;

    // ---- compact selected (exactly K) into sort arrays, pad to NP
    for (int i = t; i < NP; i += 1024) { srtIdx[i] = 0x7FFFFFFF; srtVal[i] = 0.0f; }
    __syncthreads();
    for (int i = t; i < M; i += 1024) {
        float v = pv[i];
        unsigned k = fkey(v);
        bool sel = (k > TK) || (k == TK && pi[i] <= tieThresh);
        if (sel) {
            unsigned p = atomicAdd(&sSelCount, 1u);
            if (p < (unsigned)NP) { srtIdx[p] = pi[i]; srtVal[p] = v; }
        }
    }
    __syncthreads();

    // ---- bitonic sort ascending by index (payload: value)
    for (unsigned kk = 2; kk <= (unsigned)NP; kk <<= 1) {
        for (unsigned j = kk >> 1; j > 0; j >>= 1) {
            for (int i = t; i < NP; i += 1024) {
                int l = i ^ (int)j;
                if (l > i) {
                    int  ii = srtIdx[i], il = srtIdx[l];
                    bool asc = ((i & kk) == 0);
                    if ((ii > il) == asc) {
                        srtIdx[i] = il; srtIdx[l] = ii;
                        float vi = srtVal[i];
                        srtVal[i] = srtVal[l]; srtVal[l] = vi;
                    }
                }
            }
            __syncthreads();
        }
    }

    // ---- write output (first K entries are the selected, in index order)
    for (int i = t; i < K; i += 1024) out[i] = srtVal[i];

    // ---- reset global state for next graph replay
    for (int i = t; i < BINS; i += 1024) g_hist[i] = 0;
    if (t == 0) g_cand_count = 0;
}

extern "C" void kernel_launch(void* const* d_in, const int* in_sizes, int n_in,
                              void* d_out, int out_size) {
    const float* x = (const float*)d_in[0];
    int n = in_sizes[0];
    int n4 = n / 4;
    const float4* x4 = (const float4*)x;
    int K = out_size;   // 5000
    float* out = (float*)d_out;

    const int SELECT_SMEM = SMCAP * 8 + BINS * 4 + 1024 * 4 + NP * 8;  // 180 KB
    cudaFuncSetAttribute(select_kernel,
                         cudaFuncAttributeMaxDynamicSharedMemorySize, SELECT_SMEM);

    spec_compact_kernel<<<296, 1024>>>(x4, n4, x, n);
    fallback_kernel<<<1, 1024>>>(x4, n4, x, n, K);
    select_kernel<<<1, 1024, SELECT_SMEM>>>(out, K);
}